// round 3
// baseline (speedup 1.0000x reference)
#include <cuda_runtime.h>
#include <math.h>

#define BATCH   16384
#define HID     128
#define GATES   512      // 4*HID
#define INDIM   28
#define SEQLEN  28
#define OUTDIM  10
#define TB      64       // batch rows per CTA
#define TB1     65       // padded row stride (floats) to break bank conflicts
#define NTHREADS 256

// ---------------- device scratch (transposed weights + fused biases) -----------
__device__ float g_wt_ih0[INDIM * GATES];   // [k][g]
__device__ float g_wt_hh0[HID * GATES];
__device__ float g_wt_ih1[HID * GATES];
__device__ float g_wt_hh1[HID * GATES];
__device__ float g_bias0[GATES];
__device__ float g_bias1[GATES];

// ---------------- packed fp32x2 FMA (Blackwell FFMA2, double-rate) -------------
union F2U { float2 f; unsigned long long u; };
__device__ __forceinline__ float2 ffma2(float2 a, float2 b, float2 c) {
    F2U ua, ub, uc, ud;
    ua.f = a; ub.f = b; uc.f = c;
    asm("fma.rn.f32x2 %0, %1, %2, %3;" : "=l"(ud.u) : "l"(ua.u), "l"(ub.u), "l"(uc.u));
    return ud.f;
}

__device__ __forceinline__ float sigm(float x) { return 1.0f / (1.0f + __expf(-x)); }

// ---------------- prep: transpose weights into [k][512], fuse biases ----------
__global__ void lstm_prep(const float* __restrict__ wih0, const float* __restrict__ whh0,
                          const float* __restrict__ bih0, const float* __restrict__ bhh0,
                          const float* __restrict__ wih1, const float* __restrict__ whh1,
                          const float* __restrict__ bih1, const float* __restrict__ bhh1) {
    int i = blockIdx.x * blockDim.x + threadIdx.x;
    if (i < GATES * INDIM) {
        int g = i / INDIM, k = i % INDIM;
        g_wt_ih0[k * GATES + g] = wih0[i];
    }
    if (i < GATES * HID) {
        int g = i / HID, k = i % HID;
        g_wt_hh0[k * GATES + g] = whh0[i];
        g_wt_ih1[k * GATES + g] = wih1[i];
        g_wt_hh1[k * GATES + g] = whh1[i];
    }
    if (i < GATES) {
        g_bias0[i] = bih0[i] + bhh0[i];
        g_bias1[i] = bih1[i] + bhh1[i];
    }
}

// ---------------- GEMM inner loop: acc[8 rows][8 col-pairs] += h * W^T ---------
// hs: SMEM activations [K][TB1] (plain fp32, broadcast across warp lanes)
// wt: global transposed weights [K][GATES], coalesced float4 per gate
__device__ __forceinline__ void gemm_acc(float2 (&acc)[8][8],
                                         const float* hs,
                                         const float* __restrict__ wt,
                                         int K, int rg, int cg) {
    const float* hp = hs + rg * 8;
    const float* wp = wt + cg * 4;
    #pragma unroll 4
    for (int k = 0; k < K; k++) {
        float h[8];
        #pragma unroll
        for (int r = 0; r < 8; r++) h[r] = hp[r];
        float4 w0 = *(const float4*)(wp);
        float4 w1 = *(const float4*)(wp + 128);
        float4 w2 = *(const float4*)(wp + 256);
        float4 w3 = *(const float4*)(wp + 384);
        float2 b[8] = { {w0.x, w0.y}, {w0.z, w0.w},
                        {w1.x, w1.y}, {w1.z, w1.w},
                        {w2.x, w2.y}, {w2.z, w2.w},
                        {w3.x, w3.y}, {w3.z, w3.w} };
        #pragma unroll
        for (int r = 0; r < 8; r++) {
            float2 a = make_float2(h[r], h[r]);
            #pragma unroll
            for (int c = 0; c < 8; c++) acc[r][c] = ffma2(a, b[c], acc[r][c]);
        }
        hp += TB1; wp += GATES;
    }
}

// ---------------- SMEM layout (bytes): dynamic, 139376 total -------------------
#define SM_H0   0
#define SM_H1   (HID * TB1)                // floats
#define SM_XS   (2 * HID * TB1)
#define SM_C0   (2 * HID * TB1 + INDIM * TB1)
#define SM_C1   (SM_C0 + TB * HID)
#define SM_FLOATS (SM_C1 + TB * HID)

__global__ __launch_bounds__(NTHREADS, 1)
void lstm_fused(const float* __restrict__ x,
                const float* __restrict__ fcw,
                const float* __restrict__ fcb,
                float* __restrict__ out) {
    extern __shared__ float sm[];
    float* h0s = sm + SM_H0;   // [HID][TB1]
    float* h1s = sm + SM_H1;   // [HID][TB1]
    float* xs  = sm + SM_XS;   // [INDIM][TB1]
    float* c0s = sm + SM_C0;   // [TB][HID]
    float* c1s = sm + SM_C1;   // [TB][HID]

    const int tid = threadIdx.x;
    const int rg  = tid >> 5;   // row group: rows rg*8 .. rg*8+7
    const int cg  = tid & 31;   // col group: hidden units cg*4 .. cg*4+3
    const int b0  = blockIdx.x * TB;

    // zero states
    for (int i = tid; i < HID * TB1; i += NTHREADS) { h0s[i] = 0.f; h1s[i] = 0.f; }
    for (int i = tid; i < TB * HID;  i += NTHREADS) { c0s[i] = 0.f; c1s[i] = 0.f; }
    __syncthreads();

    float2 acc[8][8];
    float  hreg[8][4];

    for (int t = 0; t < SEQLEN; t++) {
        // ---- stage x_t tile ----
        for (int i = tid; i < TB * INDIM; i += NTHREADS) {
            int r = i / INDIM, k = i % INDIM;
            xs[k * TB1 + r] = x[(size_t)(b0 + r) * (SEQLEN * INDIM) + t * INDIM + k];
        }
        __syncthreads();

        // ================= LAYER 0 =================
        #pragma unroll
        for (int cp = 0; cp < 8; cp++) {
            int gi = cp >> 1, p = cp & 1;
            float2 bv = *(const float2*)&g_bias0[gi * 128 + cg * 4 + 2 * p];
            #pragma unroll
            for (int r = 0; r < 8; r++) acc[r][cp] = bv;
        }
        gemm_acc(acc, xs,  g_wt_ih0, INDIM, rg, cg);
        gemm_acc(acc, h0s, g_wt_hh0, HID,   rg, cg);

        #pragma unroll
        for (int r = 0; r < 8; r++) {
            int row = rg * 8 + r;
            #pragma unroll
            for (int u = 0; u < 4; u++) {
                int p = u >> 1, hi = u & 1;
                float iv = hi ? acc[r][p].y     : acc[r][p].x;
                float fv = hi ? acc[r][2 + p].y : acc[r][2 + p].x;
                float gv = hi ? acc[r][4 + p].y : acc[r][4 + p].x;
                float ov = hi ? acc[r][6 + p].y : acc[r][6 + p].x;
                int j = cg * 4 + u;
                float cn = sigm(fv) * c0s[row * HID + j] + sigm(iv) * tanhf(gv);
                c0s[row * HID + j] = cn;
                hreg[r][u] = sigm(ov) * tanhf(cn);
            }
        }
        __syncthreads();   // all lanes done reading old h0s
        #pragma unroll
        for (int r = 0; r < 8; r++)
            #pragma unroll
            for (int u = 0; u < 4; u++)
                h0s[(cg * 4 + u) * TB1 + rg * 8 + r] = hreg[r][u];
        __syncthreads();   // new h0 visible

        // ================= LAYER 1 =================
        #pragma unroll
        for (int cp = 0; cp < 8; cp++) {
            int gi = cp >> 1, p = cp & 1;
            float2 bv = *(const float2*)&g_bias1[gi * 128 + cg * 4 + 2 * p];
            #pragma unroll
            for (int r = 0; r < 8; r++) acc[r][cp] = bv;
        }
        gemm_acc(acc, h0s, g_wt_ih1, HID, rg, cg);
        gemm_acc(acc, h1s, g_wt_hh1, HID, rg, cg);

        #pragma unroll
        for (int r = 0; r < 8; r++) {
            int row = rg * 8 + r;
            #pragma unroll
            for (int u = 0; u < 4; u++) {
                int p = u >> 1, hi = u & 1;
                float iv = hi ? acc[r][p].y     : acc[r][p].x;
                float fv = hi ? acc[r][2 + p].y : acc[r][2 + p].x;
                float gv = hi ? acc[r][4 + p].y : acc[r][4 + p].x;
                float ov = hi ? acc[r][6 + p].y : acc[r][6 + p].x;
                int j = cg * 4 + u;
                float cn = sigm(fv) * c1s[row * HID + j] + sigm(iv) * tanhf(gv);
                c1s[row * HID + j] = cn;
                hreg[r][u] = sigm(ov) * tanhf(cn);
            }
        }
        __syncthreads();
        #pragma unroll
        for (int r = 0; r < 8; r++)
            #pragma unroll
            for (int u = 0; u < 4; u++)
                h1s[(cg * 4 + u) * TB1 + rg * 8 + r] = hreg[r][u];
        __syncthreads();
    }

    // ---- outputs: logits [B,10], h_n [2,B,H], c_n [2,B,H] ----
    float* out_logits = out;
    float* out_h = out + (size_t)BATCH * OUTDIM;
    float* out_c = out + (size_t)BATCH * OUTDIM + 2ull * BATCH * HID;

    for (int i = tid; i < TB * HID; i += NTHREADS) {
        int r = i / HID, j = i % HID;
        out_h[(size_t)(b0 + r) * HID + j]                         = h0s[j * TB1 + r];
        out_h[(size_t)BATCH * HID + (size_t)(b0 + r) * HID + j]   = h1s[j * TB1 + r];
        out_c[(size_t)(b0 + r) * HID + j]                         = c0s[i];
        out_c[(size_t)BATCH * HID + (size_t)(b0 + r) * HID + j]   = c1s[i];
    }
    for (int i = tid; i < TB * OUTDIM; i += NTHREADS) {
        int r = i / OUTDIM, o = i % OUTDIM;
        float s = fcb[o];
        #pragma unroll 4
        for (int j = 0; j < HID; j++) s += h1s[j * TB1 + r] * fcw[o * HID + j];
        out_logits[(size_t)(b0 + r) * OUTDIM + o] = s;
    }
}

// ---------------- launch -------------------------------------------------------
extern "C" void kernel_launch(void* const* d_in, const int* in_sizes, int n_in,
                              void* d_out, int out_size) {
    const float* x     = (const float*)d_in[0];
    const float* wih0  = (const float*)d_in[1];
    const float* whh0  = (const float*)d_in[2];
    const float* bih0  = (const float*)d_in[3];
    const float* bhh0  = (const float*)d_in[4];
    const float* wih1  = (const float*)d_in[5];
    const float* whh1  = (const float*)d_in[6];
    const float* bih1  = (const float*)d_in[7];
    const float* bhh1  = (const float*)d_in[8];
    const float* fcw   = (const float*)d_in[9];
    const float* fcb   = (const float*)d_in[10];

    lstm_prep<<<(GATES * HID + 255) / 256, 256>>>(wih0, whh0, bih0, bhh0,
                                                  wih1, whh1, bih1, bhh1);

    const int smem_bytes = SM_FLOATS * (int)sizeof(float);   // 139,376 B
    cudaFuncSetAttribute(lstm_fused, cudaFuncAttributeMaxDynamicSharedMemorySize, smem_bytes);
    lstm_fused<<<BATCH / TB, NTHREADS, smem_bytes>>>(x, fcw, fcb, (float*)d_out);
}

// round 5
// speedup vs baseline: 1.1103x; 1.1103x over previous
#include <cuda_runtime.h>
#include <math.h>

#define BATCH   16384
#define HID     128
#define GATES   512      // 4*HID
#define INDIM   28
#define SEQLEN  28
#define OUTDIM  10
#define TB      64       // batch rows per CTA
#define TB1     65       // padded row stride (floats) to break bank conflicts
#define NTHREADS 512

// ---------------- device scratch (transposed weights + fused biases) -----------
__device__ float g_wt_ih0[INDIM * GATES];   // [k][g]
__device__ float g_wt_hh0[HID * GATES];
__device__ float g_wt_ih1[HID * GATES];
__device__ float g_wt_hh1[HID * GATES];
__device__ float g_bias0[GATES];
__device__ float g_bias1[GATES];

// ---------------- packed fp32x2 FMA (Blackwell FFMA2, double-rate) -------------
union F2U { float2 f; unsigned long long u; };
__device__ __forceinline__ float2 ffma2(float2 a, float2 b, float2 c) {
    F2U ua, ub, uc, ud;
    ua.f = a; ub.f = b; uc.f = c;
    asm("fma.rn.f32x2 %0, %1, %2, %3;" : "=l"(ud.u) : "l"(ua.u), "l"(ub.u), "l"(uc.u));
    return ud.f;
}

__device__ __forceinline__ float sigm(float x) { return 1.0f / (1.0f + __expf(-x)); }

// ---------------- prep: transpose weights into [k][512], fuse biases ----------
__global__ void lstm_prep(const float* __restrict__ wih0, const float* __restrict__ whh0,
                          const float* __restrict__ bih0, const float* __restrict__ bhh0,
                          const float* __restrict__ wih1, const float* __restrict__ whh1,
                          const float* __restrict__ bih1, const float* __restrict__ bhh1) {
    int i = blockIdx.x * blockDim.x + threadIdx.x;
    if (i < GATES * INDIM) {
        int g = i / INDIM, k = i % INDIM;
        g_wt_ih0[k * GATES + g] = wih0[i];
    }
    if (i < GATES * HID) {
        int g = i / HID, k = i % HID;
        g_wt_hh0[k * GATES + g] = whh0[i];
        g_wt_ih1[k * GATES + g] = wih1[i];
        g_wt_hh1[k * GATES + g] = whh1[i];
    }
    if (i < GATES) {
        g_bias0[i] = bih0[i] + bhh0[i];
        g_bias1[i] = bih1[i] + bhh1[i];
    }
}

// ---------------- GEMM inner loop: acc[8 rows][4 gates] += h * W^T -------------
// hs: SMEM activations [K][TB1] (broadcast LDS across warp)
// wt: global transposed weights [K][GATES]; each thread reads one float2 per gate
__device__ __forceinline__ void gemm_acc(float2 (&acc)[8][4],
                                         const float* hs,
                                         const float* __restrict__ wt,
                                         int K, int rg, int colbase) {
    const float* hp = hs + rg * 8;
    const float* wp = wt + colbase;
    #pragma unroll 4
    for (int k = 0; k < K; k++) {
        float h[8];
        #pragma unroll
        for (int r = 0; r < 8; r++) h[r] = hp[r];
        float2 w[4];
        #pragma unroll
        for (int g = 0; g < 4; g++) w[g] = *(const float2*)(wp + g * 128);
        #pragma unroll
        for (int r = 0; r < 8; r++) {
            float2 a = make_float2(h[r], h[r]);
            #pragma unroll
            for (int g = 0; g < 4; g++) acc[r][g] = ffma2(a, w[g], acc[r][g]);
        }
        hp += TB1; wp += GATES;
    }
}

// ---------------- SMEM layout (floats) -----------------------------------------
#define SM_H0   0
#define SM_H1   (HID * TB1)
#define SM_XS   (2 * HID * TB1)
#define SM_C0   (2 * HID * TB1 + INDIM * TB1)
#define SM_C1   (SM_C0 + TB * HID)
#define SM_FLOATS (SM_C1 + TB * HID)

__global__ __launch_bounds__(NTHREADS, 1)
void lstm_fused(const float* __restrict__ x,
                const float* __restrict__ fcw,
                const float* __restrict__ fcb,
                float* __restrict__ out) {
    extern __shared__ float sm[];
    float* h0s = sm + SM_H0;   // [HID][TB1]
    float* h1s = sm + SM_H1;   // [HID][TB1]
    float* xs  = sm + SM_XS;   // [INDIM][TB1]
    float* c0s = sm + SM_C0;   // [TB][HID]
    float* c1s = sm + SM_C1;   // [TB][HID]

    const int tid  = threadIdx.x;
    const int warp = tid >> 5;
    const int lane = tid & 31;
    const int rg   = warp & 7;          // row group: rows rg*8 .. rg*8+7
    const int half = warp >> 3;         // which 64-col half of each gate block
    const int colbase = half * 64 + lane * 2;   // within-gate column pair base
    const int b0   = blockIdx.x * TB;

    // zero states
    for (int i = tid; i < HID * TB1; i += NTHREADS) { h0s[i] = 0.f; h1s[i] = 0.f; }
    for (int i = tid; i < TB * HID;  i += NTHREADS) { c0s[i] = 0.f; c1s[i] = 0.f; }
    __syncthreads();

    float2 acc[8][4];
    float  hreg[8][2];

    for (int t = 0; t < SEQLEN; t++) {
        // ---- stage x_t tile ----
        for (int i = tid; i < TB * INDIM; i += NTHREADS) {
            int r = i / INDIM, k = i % INDIM;
            xs[k * TB1 + r] = x[(size_t)(b0 + r) * (SEQLEN * INDIM) + t * INDIM + k];
        }
        __syncthreads();

        // ================= LAYER 0 =================
        #pragma unroll
        for (int g = 0; g < 4; g++) {
            float2 bv = *(const float2*)&g_bias0[g * 128 + colbase];
            #pragma unroll
            for (int r = 0; r < 8; r++) acc[r][g] = bv;
        }
        gemm_acc(acc, xs,  g_wt_ih0, INDIM, rg, colbase);
        gemm_acc(acc, h0s, g_wt_hh0, HID,   rg, colbase);

        #pragma unroll
        for (int r = 0; r < 8; r++) {
            int row = rg * 8 + r;
            #pragma unroll
            for (int u = 0; u < 2; u++) {
                float iv = u ? acc[r][0].y : acc[r][0].x;
                float fv = u ? acc[r][1].y : acc[r][1].x;
                float gv = u ? acc[r][2].y : acc[r][2].x;
                float ov = u ? acc[r][3].y : acc[r][3].x;
                int j = colbase + u;
                float cn = sigm(fv) * c0s[row * HID + j] + sigm(iv) * tanhf(gv);
                c0s[row * HID + j] = cn;
                hreg[r][u] = sigm(ov) * tanhf(cn);
            }
        }
        __syncthreads();   // all warps done reading old h0s
        #pragma unroll
        for (int r = 0; r < 8; r++)
            #pragma unroll
            for (int u = 0; u < 2; u++)
                h0s[(colbase + u) * TB1 + rg * 8 + r] = hreg[r][u];
        __syncthreads();   // new h0 visible

        // ================= LAYER 1 =================
        #pragma unroll
        for (int g = 0; g < 4; g++) {
            float2 bv = *(const float2*)&g_bias1[g * 128 + colbase];
            #pragma unroll
            for (int r = 0; r < 8; r++) acc[r][g] = bv;
        }
        gemm_acc(acc, h0s, g_wt_ih1, HID, rg, colbase);
        gemm_acc(acc, h1s, g_wt_hh1, HID, rg, colbase);

        #pragma unroll
        for (int r = 0; r < 8; r++) {
            int row = rg * 8 + r;
            #pragma unroll
            for (int u = 0; u < 2; u++) {
                float iv = u ? acc[r][0].y : acc[r][0].x;
                float fv = u ? acc[r][1].y : acc[r][1].x;
                float gv = u ? acc[r][2].y : acc[r][2].x;
                float ov = u ? acc[r][3].y : acc[r][3].x;
                int j = colbase + u;
                float cn = sigm(fv) * c1s[row * HID + j] + sigm(iv) * tanhf(gv);
                c1s[row * HID + j] = cn;
                hreg[r][u] = sigm(ov) * tanhf(cn);
            }
        }
        __syncthreads();
        #pragma unroll
        for (int r = 0; r < 8; r++)
            #pragma unroll
            for (int u = 0; u < 2; u++)
                h1s[(colbase + u) * TB1 + rg * 8 + r] = hreg[r][u];
        __syncthreads();
    }

    // ---- outputs: logits [B,10], h_n [2,B,H], c_n [2,B,H] ----
    float* out_logits = out;
    float* out_h = out + (size_t)BATCH * OUTDIM;
    float* out_c = out + (size_t)BATCH * OUTDIM + 2ull * BATCH * HID;

    for (int i = tid; i < TB * HID; i += NTHREADS) {
        int r = i / HID, j = i % HID;
        out_h[(size_t)(b0 + r) * HID + j]                         = h0s[j * TB1 + r];
        out_h[(size_t)BATCH * HID + (size_t)(b0 + r) * HID + j]   = h1s[j * TB1 + r];
        out_c[(size_t)(b0 + r) * HID + j]                         = c0s[i];
        out_c[(size_t)BATCH * HID + (size_t)(b0 + r) * HID + j]   = c1s[i];
    }
    for (int i = tid; i < TB * OUTDIM; i += NTHREADS) {
        int r = i / OUTDIM, o = i % OUTDIM;
        float s = fcb[o];
        #pragma unroll 4
        for (int j = 0; j < HID; j++) s += h1s[j * TB1 + r] * fcw[o * HID + j];
        out_logits[(size_t)(b0 + r) * OUTDIM + o] = s;
    }
}

// ---------------- launch -------------------------------------------------------
extern "C" void kernel_launch(void* const* d_in, const int* in_sizes, int n_in,
                              void* d_out, int out_size) {
    const float* x     = (const float*)d_in[0];
    const float* wih0  = (const float*)d_in[1];
    const float* whh0  = (const float*)d_in[2];
    const float* bih0  = (const float*)d_in[3];
    const float* bhh0  = (const float*)d_in[4];
    const float* wih1  = (const float*)d_in[5];
    const float* whh1  = (const float*)d_in[6];
    const float* bih1  = (const float*)d_in[7];
    const float* bhh1  = (const float*)d_in[8];
    const float* fcw   = (const float*)d_in[9];
    const float* fcb   = (const float*)d_in[10];

    lstm_prep<<<(GATES * HID + 255) / 256, 256>>>(wih0, whh0, bih0, bhh0,
                                                  wih1, whh1, bih1, bhh1);

    const int smem_bytes = SM_FLOATS * (int)sizeof(float);   // 139,376 B
    cudaFuncSetAttribute(lstm_fused, cudaFuncAttributeMaxDynamicSharedMemorySize, smem_bytes);
    lstm_fused<<<BATCH / TB, NTHREADS, smem_bytes>>>(x, fcw, fcb, (float*)d_out);
}

// round 6
// speedup vs baseline: 1.1104x; 1.0001x over previous
#include <cuda_runtime.h>
#include <math.h>

#define BATCH   16384
#define HID     128
#define GATES   512      // 4*HID
#define INDIM   28
#define SEQLEN  28
#define OUTDIM  10
#define TB      64       // batch rows per CTA
#define TB1     65       // padded row stride (floats) to break bank conflicts
#define NTHREADS 512

// ---------------- device scratch (transposed weights + fused biases) -----------
__device__ float g_wt_ih0[INDIM * GATES];   // [k][g]
__device__ float g_wt_hh0[HID * GATES];
__device__ float g_wt_ih1[HID * GATES];
__device__ float g_wt_hh1[HID * GATES];
__device__ float g_bias0[GATES];
__device__ float g_bias1[GATES];

// ---------------- packed fp32x2 FMA (Blackwell FFMA2, double-rate) -------------
union F2U { float2 f; unsigned long long u; };
__device__ __forceinline__ float2 ffma2(float2 a, float2 b, float2 c) {
    F2U ua, ub, uc, ud;
    ua.f = a; ub.f = b; uc.f = c;
    asm("fma.rn.f32x2 %0, %1, %2, %3;" : "=l"(ud.u) : "l"(ua.u), "l"(ub.u), "l"(uc.u));
    return ud.f;
}

__device__ __forceinline__ float sigm(float x) { return 1.0f / (1.0f + __expf(-x)); }

// ---------------- prep: transpose weights into [k][512], fuse biases ----------
__global__ void lstm_prep(const float* __restrict__ wih0, const float* __restrict__ whh0,
                          const float* __restrict__ bih0, const float* __restrict__ bhh0,
                          const float* __restrict__ wih1, const float* __restrict__ whh1,
                          const float* __restrict__ bih1, const float* __restrict__ bhh1) {
    int i = blockIdx.x * blockDim.x + threadIdx.x;
    if (i < GATES * INDIM) {
        int g = i / INDIM, k = i % INDIM;
        g_wt_ih0[k * GATES + g] = wih0[i];
    }
    if (i < GATES * HID) {
        int g = i / HID, k = i % HID;
        g_wt_hh0[k * GATES + g] = whh0[i];
        g_wt_ih1[k * GATES + g] = wih1[i];
        g_wt_hh1[k * GATES + g] = whh1[i];
    }
    if (i < GATES) {
        g_bias0[i] = bih0[i] + bhh0[i];
        g_bias1[i] = bih1[i] + bhh1[i];
    }
}

// ---------------- GEMM inner loop: acc[8 rows][4 gates] += h * W^T -------------
// hs: SMEM activations [K][TB1] (broadcast LDS across warp)
// wt: global transposed weights [K][GATES]; each thread reads one float2 per gate
__device__ __forceinline__ void gemm_acc(float2 (&acc)[8][4],
                                         const float* hs,
                                         const float* __restrict__ wt,
                                         int K, int rg, int colbase) {
    const float* hp = hs + rg * 8;
    const float* wp = wt + colbase;
    #pragma unroll 4
    for (int k = 0; k < K; k++) {
        float h[8];
        #pragma unroll
        for (int r = 0; r < 8; r++) h[r] = hp[r];
        float2 w[4];
        #pragma unroll
        for (int g = 0; g < 4; g++) w[g] = *(const float2*)(wp + g * 128);
        #pragma unroll
        for (int r = 0; r < 8; r++) {
            float2 a = make_float2(h[r], h[r]);
            #pragma unroll
            for (int g = 0; g < 4; g++) acc[r][g] = ffma2(a, w[g], acc[r][g]);
        }
        hp += TB1; wp += GATES;
    }
}

// ---------------- SMEM layout (floats) -----------------------------------------
#define SM_H0   0
#define SM_H1   (HID * TB1)
#define SM_XS   (2 * HID * TB1)
#define SM_C0   (2 * HID * TB1 + INDIM * TB1)
#define SM_C1   (SM_C0 + TB * HID)
#define SM_FLOATS (SM_C1 + TB * HID)

__global__ __launch_bounds__(NTHREADS, 1)
void lstm_fused(const float* __restrict__ x,
                const float* __restrict__ fcw,
                const float* __restrict__ fcb,
                float* __restrict__ out) {
    extern __shared__ float sm[];
    float* h0s = sm + SM_H0;   // [HID][TB1]
    float* h1s = sm + SM_H1;   // [HID][TB1]
    float* xs  = sm + SM_XS;   // [INDIM][TB1]
    float* c0s = sm + SM_C0;   // [TB][HID]
    float* c1s = sm + SM_C1;   // [TB][HID]

    const int tid  = threadIdx.x;
    const int warp = tid >> 5;
    const int lane = tid & 31;
    const int rg   = warp & 7;          // row group: rows rg*8 .. rg*8+7
    const int half = warp >> 3;         // which 64-col half of each gate block
    const int colbase = half * 64 + lane * 2;   // within-gate column pair base
    const int b0   = blockIdx.x * TB;

    // zero states
    for (int i = tid; i < HID * TB1; i += NTHREADS) { h0s[i] = 0.f; h1s[i] = 0.f; }
    for (int i = tid; i < TB * HID;  i += NTHREADS) { c0s[i] = 0.f; c1s[i] = 0.f; }
    __syncthreads();

    float2 acc[8][4];
    float  hreg[8][2];

    for (int t = 0; t < SEQLEN; t++) {
        // ---- stage x_t tile ----
        for (int i = tid; i < TB * INDIM; i += NTHREADS) {
            int r = i / INDIM, k = i % INDIM;
            xs[k * TB1 + r] = x[(size_t)(b0 + r) * (SEQLEN * INDIM) + t * INDIM + k];
        }
        __syncthreads();

        // ================= LAYER 0 =================
        #pragma unroll
        for (int g = 0; g < 4; g++) {
            float2 bv = *(const float2*)&g_bias0[g * 128 + colbase];
            #pragma unroll
            for (int r = 0; r < 8; r++) acc[r][g] = bv;
        }
        gemm_acc(acc, xs,  g_wt_ih0, INDIM, rg, colbase);
        gemm_acc(acc, h0s, g_wt_hh0, HID,   rg, colbase);

        #pragma unroll
        for (int r = 0; r < 8; r++) {
            int row = rg * 8 + r;
            #pragma unroll
            for (int u = 0; u < 2; u++) {
                float iv = u ? acc[r][0].y : acc[r][0].x;
                float fv = u ? acc[r][1].y : acc[r][1].x;
                float gv = u ? acc[r][2].y : acc[r][2].x;
                float ov = u ? acc[r][3].y : acc[r][3].x;
                int j = colbase + u;
                float cn = sigm(fv) * c0s[row * HID + j] + sigm(iv) * tanhf(gv);
                c0s[row * HID + j] = cn;
                hreg[r][u] = sigm(ov) * tanhf(cn);
            }
        }
        __syncthreads();   // all warps done reading old h0s
        #pragma unroll
        for (int r = 0; r < 8; r++)
            #pragma unroll
            for (int u = 0; u < 2; u++)
                h0s[(colbase + u) * TB1 + rg * 8 + r] = hreg[r][u];
        __syncthreads();   // new h0 visible

        // ================= LAYER 1 =================
        #pragma unroll
        for (int g = 0; g < 4; g++) {
            float2 bv = *(const float2*)&g_bias1[g * 128 + colbase];
            #pragma unroll
            for (int r = 0; r < 8; r++) acc[r][g] = bv;
        }
        gemm_acc(acc, h0s, g_wt_ih1, HID, rg, colbase);
        gemm_acc(acc, h1s, g_wt_hh1, HID, rg, colbase);

        #pragma unroll
        for (int r = 0; r < 8; r++) {
            int row = rg * 8 + r;
            #pragma unroll
            for (int u = 0; u < 2; u++) {
                float iv = u ? acc[r][0].y : acc[r][0].x;
                float fv = u ? acc[r][1].y : acc[r][1].x;
                float gv = u ? acc[r][2].y : acc[r][2].x;
                float ov = u ? acc[r][3].y : acc[r][3].x;
                int j = colbase + u;
                float cn = sigm(fv) * c1s[row * HID + j] + sigm(iv) * tanhf(gv);
                c1s[row * HID + j] = cn;
                hreg[r][u] = sigm(ov) * tanhf(cn);
            }
        }
        __syncthreads();
        #pragma unroll
        for (int r = 0; r < 8; r++)
            #pragma unroll
            for (int u = 0; u < 2; u++)
                h1s[(colbase + u) * TB1 + rg * 8 + r] = hreg[r][u];
        __syncthreads();
    }

    // ---- outputs: logits [B,10], h_n [2,B,H], c_n [2,B,H] ----
    float* out_logits = out;
    float* out_h = out + (size_t)BATCH * OUTDIM;
    float* out_c = out + (size_t)BATCH * OUTDIM + 2ull * BATCH * HID;

    for (int i = tid; i < TB * HID; i += NTHREADS) {
        int r = i / HID, j = i % HID;
        out_h[(size_t)(b0 + r) * HID + j]                         = h0s[j * TB1 + r];
        out_h[(size_t)BATCH * HID + (size_t)(b0 + r) * HID + j]   = h1s[j * TB1 + r];
        out_c[(size_t)(b0 + r) * HID + j]                         = c0s[i];
        out_c[(size_t)BATCH * HID + (size_t)(b0 + r) * HID + j]   = c1s[i];
    }
    for (int i = tid; i < TB * OUTDIM; i += NTHREADS) {
        int r = i / OUTDIM, o = i % OUTDIM;
        float s = fcb[o];
        #pragma unroll 4
        for (int j = 0; j < HID; j++) s += h1s[j * TB1 + r] * fcw[o * HID + j];
        out_logits[(size_t)(b0 + r) * OUTDIM + o] = s;
    }
}

// ---------------- launch -------------------------------------------------------
extern "C" void kernel_launch(void* const* d_in, const int* in_sizes, int n_in,
                              void* d_out, int out_size) {
    const float* x     = (const float*)d_in[0];
    const float* wih0  = (const float*)d_in[1];
    const float* whh0  = (const float*)d_in[2];
    const float* bih0  = (const float*)d_in[3];
    const float* bhh0  = (const float*)d_in[4];
    const float* wih1  = (const float*)d_in[5];
    const float* whh1  = (const float*)d_in[6];
    const float* bih1  = (const float*)d_in[7];
    const float* bhh1  = (const float*)d_in[8];
    const float* fcw   = (const float*)d_in[9];
    const float* fcb   = (const float*)d_in[10];

    lstm_prep<<<(GATES * HID + 255) / 256, 256>>>(wih0, whh0, bih0, bhh0,
                                                  wih1, whh1, bih1, bhh1);

    const int smem_bytes = SM_FLOATS * (int)sizeof(float);   // 139,376 B
    cudaFuncSetAttribute(lstm_fused, cudaFuncAttributeMaxDynamicSharedMemorySize, smem_bytes);
    lstm_fused<<<BATCH / TB, NTHREADS, smem_bytes>>>(x, fcw, fcb, (float*)d_out);
}

// round 8
// speedup vs baseline: 2.9550x; 2.6611x over previous
#include <cuda_runtime.h>
#include <cuda_bf16.h>
#include <stdint.h>
#include <math.h>

#define BATCH  16384
#define HID    128
#define SEQ    28
#define INDIM  28
#define OUTDIM 10
#define MR     64       // batch rows per CTA
#define NT     256
#define HSTRIDE 272     // h tile row stride bytes (136 bf16) — ldsm conflict-free
#define XSTRIDE 80      // x tile row stride bytes (40 bf16)
#define HT_SZ  (64 * HSTRIDE)            // 17408 B per h tile
#define SM_X   (8 * HT_SZ)               // x tiles after 8 h tiles
#define SMEM_BYTES (SM_X + 2 * 64 * XSTRIDE)   // 149504

// h tile offset: layer L, buffer b, precision p (0=hi,1=lo)
#define HT_OFF(L, b, p) ((((L) * 2 + (b)) * 2 + (p)) * HT_SZ)

// ---- prepped weights: exact mma.m16n8k16 B-fragment order ----
// layout per matrix section: [(c*8+wn)*KS + ks][lane][8 regs(uint32)]
// reg r = nf*2 + b : packed bf16 pair (k0, k0+1), k0 = ks*16 + (lane&3)*2 + b*8,
//                    n'' = wn*32 + nf*8 + lane/4,  n = (n''&3)*128 + c*64 + (n''>>2)
#define SEC_IH0 0
#define SEC_HH0 8192
#define SEC_IH1 40960
#define SEC_HH1 73728
#define W_TOTAL 106496
__device__ uint32_t g_Whi[W_TOTAL];
__device__ uint32_t g_Wlo[W_TOTAL];
__device__ float    g_bfrag[2 * 2 * 8 * 32 * 8];   // [L][c][wn][lane][8]

// ---------------- helpers ----------------
__device__ __forceinline__ uint32_t smem_u32(const void* p) {
    uint32_t a;
    asm("{ .reg .u64 t; cvta.to.shared.u64 t, %1; cvt.u32.u64 %0, t; }" : "=r"(a) : "l"(p));
    return a;
}
__device__ __forceinline__ void ldsm4(uint32_t* r, uint32_t addr) {
    asm volatile("ldmatrix.sync.aligned.m8n8.x4.shared.b16 {%0,%1,%2,%3}, [%4];"
                 : "=r"(r[0]), "=r"(r[1]), "=r"(r[2]), "=r"(r[3]) : "r"(addr));
}
__device__ __forceinline__ void mma16816(float* d, const uint32_t* a, uint32_t b0, uint32_t b1) {
    asm volatile("mma.sync.aligned.m16n8k16.row.col.f32.bf16.bf16.f32 "
                 "{%0,%1,%2,%3}, {%4,%5,%6,%7}, {%8,%9}, {%0,%1,%2,%3};"
                 : "+f"(d[0]), "+f"(d[1]), "+f"(d[2]), "+f"(d[3])
                 : "r"(a[0]), "r"(a[1]), "r"(a[2]), "r"(a[3]), "r"(b0), "r"(b1));
}
__device__ __forceinline__ float sigm(float x) {
    float e = __expf(-x);
    return __fdividef(1.0f, 1.0f + e);
}
__device__ __forceinline__ float tanha(float x) {
    float e = __expf(2.0f * x);
    return 1.0f - __fdividef(2.0f, e + 1.0f);
}

// ---------------- prep: weights -> B-fragments (hi/lo), bias -> C-fragments ----
__global__ void lstm_prep(const float* __restrict__ wih0, const float* __restrict__ whh0,
                          const float* __restrict__ bih0, const float* __restrict__ bhh0,
                          const float* __restrict__ wih1, const float* __restrict__ whh1,
                          const float* __restrict__ bih1, const float* __restrict__ bhh1) {
    int i = blockIdx.x * blockDim.x + threadIdx.x;
    if (i < W_TOTAL) {
        const float* W; int realK, KS, li;
        if      (i < SEC_HH0) { W = wih0; realK = INDIM; KS = 2; li = i; }
        else if (i < SEC_IH1) { W = whh0; realK = 128;   KS = 8; li = i - SEC_HH0; }
        else if (i < SEC_HH1) { W = wih1; realK = 128;   KS = 8; li = i - SEC_IH1; }
        else                  { W = whh1; realK = 128;   KS = 8; li = i - SEC_HH1; }
        int reg = li & 7, lane = (li >> 3) & 31;
        int ks = (li >> 8) % KS, rest = (li >> 8) / KS;
        int wn = rest & 7, c = rest >> 3;
        int nf = reg >> 1, b = reg & 1;
        int npp = wn * 32 + nf * 8 + (lane >> 2);
        int n = (npp & 3) * 128 + c * 64 + (npp >> 2);
        int k0 = ks * 16 + (lane & 3) * 2 + b * 8;
        float w0 = (k0     < realK) ? W[n * realK + k0]     : 0.0f;
        float w1 = (k0 + 1 < realK) ? W[n * realK + k0 + 1] : 0.0f;
        __nv_bfloat16 h0 = __float2bfloat16(w0), h1 = __float2bfloat16(w1);
        __nv_bfloat16 l0 = __float2bfloat16(w0 - __bfloat162float(h0));
        __nv_bfloat16 l1 = __float2bfloat16(w1 - __bfloat162float(h1));
        g_Whi[i] = (uint32_t)__bfloat16_as_ushort(h0) | ((uint32_t)__bfloat16_as_ushort(h1) << 16);
        g_Wlo[i] = (uint32_t)__bfloat16_as_ushort(l0) | ((uint32_t)__bfloat16_as_ushort(l1) << 16);
    } else if (i < W_TOTAL + 8192) {
        int li = i - W_TOTAL;
        int reg = li & 7, lane = (li >> 3) & 31, wn = (li >> 8) & 7, c = (li >> 11) & 1, L = li >> 12;
        int npp = wn * 32 + (reg >> 1) * 8 + (lane & 3) * 2 + (reg & 1);
        int gj = (npp & 3) * 128 + c * 64 + (npp >> 2);
        g_bfrag[li] = L ? (bih1[gj] + bhh1[gj]) : (bih0[gj] + bhh0[gj]);
    }
}

// ---------------- K-loop: acc += Ahi*Bhi + Alo*Bhi + Ahi*Blo --------------------
template <int KS>
__device__ __forceinline__ void mma_block(float (&acc)[4][4][4],
                                          const uint32_t* __restrict__ bhi,
                                          const uint32_t* __restrict__ blo,
                                          uint32_t aHi, uint32_t aLo, int stride)
{
    #pragma unroll
    for (int ks = 0; ks < KS; ks++) {
        uint4 BH0 = *(const uint4*)(bhi + ks * 256);
        uint4 BH1 = *(const uint4*)(bhi + ks * 256 + 4);
        uint4 BL0 = *(const uint4*)(blo + ks * 256);
        uint4 BL1 = *(const uint4*)(blo + ks * 256 + 4);
        uint32_t BH[8] = {BH0.x, BH0.y, BH0.z, BH0.w, BH1.x, BH1.y, BH1.z, BH1.w};
        uint32_t BL[8] = {BL0.x, BL0.y, BL0.z, BL0.w, BL1.x, BL1.y, BL1.z, BL1.w};
        #pragma unroll
        for (int mf = 0; mf < 4; mf++) {
            uint32_t AH[4], AL[4];
            ldsm4(AH, aHi + mf * 16 * stride + ks * 32);
            ldsm4(AL, aLo + mf * 16 * stride + ks * 32);
            #pragma unroll
            for (int nf = 0; nf < 4; nf++) {
                mma16816(acc[mf][nf], AH, BH[nf * 2], BH[nf * 2 + 1]);
                mma16816(acc[mf][nf], AL, BH[nf * 2], BH[nf * 2 + 1]);
                mma16816(acc[mf][nf], AH, BL[nf * 2], BL[nf * 2 + 1]);
            }
        }
    }
}

__device__ __forceinline__ void init_bias(float (&acc)[4][4][4], int L, int c, int wn, int lane) {
    const float4* bp = (const float4*)(g_bfrag + (((L * 2 + c) * 8 + wn) * 32 + lane) * 8);
    float4 v0 = bp[0], v1 = bp[1];
    float bf[8] = {v0.x, v0.y, v0.z, v0.w, v1.x, v1.y, v1.z, v1.w};
    #pragma unroll
    for (int mf = 0; mf < 4; mf++)
        #pragma unroll
        for (int nf = 0; nf < 4; nf++) {
            acc[mf][nf][0] = bf[nf * 2];
            acc[mf][nf][1] = bf[nf * 2 + 1];
            acc[mf][nf][2] = bf[nf * 2];
            acc[mf][nf][3] = bf[nf * 2 + 1];
        }
}

__device__ __forceinline__ void epilogue(float (&acc)[4][4][4], float (&cst)[64], int cbase,
                                         int c, int wn, int quad, int qid, bool ev, char* smc,
                                         uint32_t wHi, uint32_t wLo, bool last,
                                         float* outH, float* outC, int b0)
{
    #pragma unroll
    for (int mf = 0; mf < 4; mf++)
        #pragma unroll
        for (int nf = 0; nf < 4; nf++) {
            float a0 = acc[mf][nf][0], a1 = acc[mf][nf][1];
            float a2 = acc[mf][nf][2], a3 = acc[mf][nf][3];
            float e1 = __shfl_xor_sync(0xffffffffu, ev ? a2 : a0, 1);
            float e2 = __shfl_xor_sync(0xffffffffu, ev ? a3 : a1, 1);
            float gi = ev ? a0 : e1;
            float gf = ev ? a1 : e2;
            float gg = ev ? e1 : a2;
            float go = ev ? e2 : a3;
            float cold = cst[cbase + mf * 4 + nf];
            float cn = sigm(gf) * cold + sigm(gi) * tanha(gg);
            cst[cbase + mf * 4 + nf] = cn;
            float h = sigm(go) * tanha(cn);
            int row = mf * 16 + quad + (ev ? 0 : 8);
            int j = c * 64 + wn * 8 + nf * 2 + (qid >> 1);
            __nv_bfloat16 hh = __float2bfloat16(h);
            __nv_bfloat16 hl = __float2bfloat16(h - __bfloat162float(hh));
            *(__nv_bfloat16*)(smc + wHi + row * HSTRIDE + j * 2) = hh;
            *(__nv_bfloat16*)(smc + wLo + row * HSTRIDE + j * 2) = hl;
            if (last) {
                outH[(size_t)(b0 + row) * HID + j] = h;
                outC[(size_t)(b0 + row) * HID + j] = cn;
            }
        }
}

// ---------------- main fused kernel ---------------------------------------------
__global__ __launch_bounds__(NT, 1)
void lstm_mma(const float* __restrict__ x,
              const float* __restrict__ fcw,
              const float* __restrict__ fcb,
              float* __restrict__ out)
{
    extern __shared__ __align__(128) char smc[];
    const uint32_t sb = smem_u32(smc);
    const int tid = threadIdx.x;
    const int wn = tid >> 5, lane = tid & 31;
    const int quad = lane >> 2, qid = lane & 3;
    const bool ev = !(qid & 1);
    const int b0 = blockIdx.x * MR;

    // zero all smem (x pad cols + initial h/c state)
    for (int i = tid; i < SMEM_BYTES / 4; i += NT) ((uint32_t*)smc)[i] = 0;
    __syncthreads();

    float cst[64];
    #pragma unroll
    for (int i = 0; i < 64; i++) cst[i] = 0.0f;

    float* outLog = out;
    float* outH = out + (size_t)BATCH * OUTDIM;
    float* outC = outH + 2ull * BATCH * HID;

    const uint32_t laneH = (lane & 15) * HSTRIDE + (lane >> 4) * 16;
    const uint32_t laneX = (lane & 15) * XSTRIDE + (lane >> 4) * 16;

    for (int t = 0; t < SEQ; t++) {
        const int pb = t & 1;
        // ---- stage x_t (bf16 hi/lo) ----
        for (int i = tid; i < MR * INDIM; i += NT) {
            int r = i / INDIM, k = i - r * INDIM;
            float v = x[(size_t)(b0 + r) * (SEQ * INDIM) + t * INDIM + k];
            __nv_bfloat16 hi = __float2bfloat16(v);
            __nv_bfloat16 lo = __float2bfloat16(v - __bfloat162float(hi));
            *(__nv_bfloat16*)(smc + SM_X + r * XSTRIDE + k * 2) = hi;
            *(__nv_bfloat16*)(smc + SM_X + 64 * XSTRIDE + r * XSTRIDE + k * 2) = lo;
        }
        __syncthreads();

        const bool last = (t == SEQ - 1);
        const uint32_t h0rHi = HT_OFF(0, pb, 0),     h0rLo = HT_OFF(0, pb, 1);
        const uint32_t h0wHi = HT_OFF(0, pb ^ 1, 0), h0wLo = HT_OFF(0, pb ^ 1, 1);
        const uint32_t h1rHi = HT_OFF(1, pb, 0),     h1rLo = HT_OFF(1, pb, 1);
        const uint32_t h1wHi = HT_OFF(1, pb ^ 1, 0), h1wLo = HT_OFF(1, pb ^ 1, 1);

        // ============ LAYER 0 ============
        #pragma unroll
        for (int c = 0; c < 2; c++) {
            float acc[4][4][4];
            init_bias(acc, 0, c, wn, lane);
            mma_block<2>(acc, g_Whi + SEC_IH0 + ((c * 8 + wn) * 2) * 256 + lane * 8,
                              g_Wlo + SEC_IH0 + ((c * 8 + wn) * 2) * 256 + lane * 8,
                         sb + SM_X + laneX, sb + SM_X + 64 * XSTRIDE + laneX, XSTRIDE);
            mma_block<8>(acc, g_Whi + SEC_HH0 + ((c * 8 + wn) * 8) * 256 + lane * 8,
                              g_Wlo + SEC_HH0 + ((c * 8 + wn) * 8) * 256 + lane * 8,
                         sb + h0rHi + laneH, sb + h0rLo + laneH, HSTRIDE);
            epilogue(acc, cst, c * 16, c, wn, quad, qid, ev, smc,
                     h0wHi, h0wLo, last, outH, outC, b0);
        }
        __syncthreads();   // h0(new) complete before L1 reads it

        // ============ LAYER 1 ============
        #pragma unroll
        for (int c = 0; c < 2; c++) {
            float acc[4][4][4];
            init_bias(acc, 1, c, wn, lane);
            mma_block<8>(acc, g_Whi + SEC_IH1 + ((c * 8 + wn) * 8) * 256 + lane * 8,
                              g_Wlo + SEC_IH1 + ((c * 8 + wn) * 8) * 256 + lane * 8,
                         sb + h0wHi + laneH, sb + h0wLo + laneH, HSTRIDE);
            mma_block<8>(acc, g_Whi + SEC_HH1 + ((c * 8 + wn) * 8) * 256 + lane * 8,
                              g_Wlo + SEC_HH1 + ((c * 8 + wn) * 8) * 256 + lane * 8,
                         sb + h1rHi + laneH, sb + h1rLo + laneH, HSTRIDE);
            epilogue(acc, cst, 32 + c * 16, c, wn, quad, qid, ev, smc,
                     h1wHi, h1wLo, last, outH + (size_t)BATCH * HID,
                     outC + (size_t)BATCH * HID, b0);
        }
        __syncthreads();   // h1(new) + all writes done before next stage/FC
    }

    // ---- FC head from final h1 (buffer 0 after t=27) ----
    {
        const char* hHi = smc + HT_OFF(1, 0, 0);
        const char* hLo = smc + HT_OFF(1, 0, 1);
        for (int i = tid; i < MR * OUTDIM; i += NT) {
            int r = i / OUTDIM, o = i - r * OUTDIM;
            float s = fcb[o];
            #pragma unroll 4
            for (int j = 0; j < HID; j++) {
                float hv = __bfloat162float(*(const __nv_bfloat16*)(hHi + r * HSTRIDE + j * 2))
                         + __bfloat162float(*(const __nv_bfloat16*)(hLo + r * HSTRIDE + j * 2));
                s += hv * fcw[o * HID + j];
            }
            outLog[(size_t)(b0 + r) * OUTDIM + o] = s;
        }
    }
}

// ---------------- launch ----------------------------------------------------------
extern "C" void kernel_launch(void* const* d_in, const int* in_sizes, int n_in,
                              void* d_out, int out_size) {
    const float* x    = (const float*)d_in[0];
    const float* wih0 = (const float*)d_in[1];
    const float* whh0 = (const float*)d_in[2];
    const float* bih0 = (const float*)d_in[3];
    const float* bhh0 = (const float*)d_in[4];
    const float* wih1 = (const float*)d_in[5];
    const float* whh1 = (const float*)d_in[6];
    const float* bih1 = (const float*)d_in[7];
    const float* bhh1 = (const float*)d_in[8];
    const float* fcw  = (const float*)d_in[9];
    const float* fcb  = (const float*)d_in[10];

    lstm_prep<<<(W_TOTAL + 8192 + 255) / 256, 256>>>(wih0, whh0, bih0, bhh0,
                                                     wih1, whh1, bih1, bhh1);

    cudaFuncSetAttribute(lstm_mma, cudaFuncAttributeMaxDynamicSharedMemorySize, SMEM_BYTES);
    lstm_mma<<<BATCH / MR, NT, SMEM_BYTES>>>(x, fcw, fcb, (float*)d_out);
}

// round 9
// speedup vs baseline: 3.3156x; 1.1220x over previous
#include <cuda_runtime.h>
#include <cuda_bf16.h>
#include <stdint.h>
#include <math.h>

#define BATCH  16384
#define HID    128
#define SEQ    28
#define INDIM  28
#define OUTDIM 10
#define MR     32       // batch rows per CTA (halved: 2 CTAs/SM)
#define NT     256
#define HSTRIDE 272     // h tile row stride bytes (136 bf16) — ldsm conflict-free
#define XSTRIDE 80      // x tile row stride bytes (40 bf16)
#define HT_SZ  (MR * HSTRIDE)            // 8704 B per h tile
#define SM_X   (8 * HT_SZ)               // x tiles after 8 h tiles
#define SMEM_BYTES (SM_X + 2 * MR * XSTRIDE)   // 74752

// h tile offset: layer L, buffer b, precision p (0=hi,1=lo)
#define HT_OFF(L, b, p) ((((L) * 2 + (b)) * 2 + (p)) * HT_SZ)

// ---- prepped weights: exact mma.m16n8k16 B-fragment order ----
// layout per matrix section: [(c*8+wn)*KS + ks][lane][8 regs(uint32)]
// reg r = nf*2 + b : packed bf16 pair (k0, k0+1), k0 = ks*16 + (lane&3)*2 + b*8,
//                    n'' = wn*32 + nf*8 + lane/4,  n = (n''&3)*128 + c*64 + (n''>>2)
#define SEC_IH0 0
#define SEC_HH0 8192
#define SEC_IH1 40960
#define SEC_HH1 73728
#define W_TOTAL 106496
__device__ uint32_t g_Whi[W_TOTAL];
__device__ uint32_t g_Wlo[W_TOTAL];
__device__ float    g_bfrag[2 * 2 * 8 * 32 * 8];   // [L][c][wn][lane][8]

// ---------------- helpers ----------------
__device__ __forceinline__ uint32_t smem_u32(const void* p) {
    uint32_t a;
    asm("{ .reg .u64 t; cvta.to.shared.u64 t, %1; cvt.u32.u64 %0, t; }" : "=r"(a) : "l"(p));
    return a;
}
__device__ __forceinline__ void ldsm4(uint32_t* r, uint32_t addr) {
    asm volatile("ldmatrix.sync.aligned.m8n8.x4.shared.b16 {%0,%1,%2,%3}, [%4];"
                 : "=r"(r[0]), "=r"(r[1]), "=r"(r[2]), "=r"(r[3]) : "r"(addr));
}
__device__ __forceinline__ void mma16816(float* d, const uint32_t* a, uint32_t b0, uint32_t b1) {
    asm volatile("mma.sync.aligned.m16n8k16.row.col.f32.bf16.bf16.f32 "
                 "{%0,%1,%2,%3}, {%4,%5,%6,%7}, {%8,%9}, {%0,%1,%2,%3};"
                 : "+f"(d[0]), "+f"(d[1]), "+f"(d[2]), "+f"(d[3])
                 : "r"(a[0]), "r"(a[1]), "r"(a[2]), "r"(a[3]), "r"(b0), "r"(b1));
}
__device__ __forceinline__ float sigm(float x) {
    float e = __expf(-x);
    return __fdividef(1.0f, 1.0f + e);
}
__device__ __forceinline__ float tanha(float x) {
    float e = __expf(2.0f * x);
    return 1.0f - __fdividef(2.0f, e + 1.0f);
}

// ---------------- prep: weights -> B-fragments (hi/lo), bias -> C-fragments ----
__global__ void lstm_prep(const float* __restrict__ wih0, const float* __restrict__ whh0,
                          const float* __restrict__ bih0, const float* __restrict__ bhh0,
                          const float* __restrict__ wih1, const float* __restrict__ whh1,
                          const float* __restrict__ bih1, const float* __restrict__ bhh1) {
    int i = blockIdx.x * blockDim.x + threadIdx.x;
    if (i < W_TOTAL) {
        const float* W; int realK, KS, li;
        if      (i < SEC_HH0) { W = wih0; realK = INDIM; KS = 2; li = i; }
        else if (i < SEC_IH1) { W = whh0; realK = 128;   KS = 8; li = i - SEC_HH0; }
        else if (i < SEC_HH1) { W = wih1; realK = 128;   KS = 8; li = i - SEC_IH1; }
        else                  { W = whh1; realK = 128;   KS = 8; li = i - SEC_HH1; }
        int reg = li & 7, lane = (li >> 3) & 31;
        int ks = (li >> 8) % KS, rest = (li >> 8) / KS;
        int wn = rest & 7, c = rest >> 3;
        int nf = reg >> 1, b = reg & 1;
        int npp = wn * 32 + nf * 8 + (lane >> 2);
        int n = (npp & 3) * 128 + c * 64 + (npp >> 2);
        int k0 = ks * 16 + (lane & 3) * 2 + b * 8;
        float w0 = (k0     < realK) ? W[n * realK + k0]     : 0.0f;
        float w1 = (k0 + 1 < realK) ? W[n * realK + k0 + 1] : 0.0f;
        __nv_bfloat16 h0 = __float2bfloat16(w0), h1 = __float2bfloat16(w1);
        __nv_bfloat16 l0 = __float2bfloat16(w0 - __bfloat162float(h0));
        __nv_bfloat16 l1 = __float2bfloat16(w1 - __bfloat162float(h1));
        g_Whi[i] = (uint32_t)__bfloat16_as_ushort(h0) | ((uint32_t)__bfloat16_as_ushort(h1) << 16);
        g_Wlo[i] = (uint32_t)__bfloat16_as_ushort(l0) | ((uint32_t)__bfloat16_as_ushort(l1) << 16);
    } else if (i < W_TOTAL + 8192) {
        int li = i - W_TOTAL;
        int reg = li & 7, lane = (li >> 3) & 31, wn = (li >> 8) & 7, c = (li >> 11) & 1, L = li >> 12;
        int npp = wn * 32 + (reg >> 1) * 8 + (lane & 3) * 2 + (reg & 1);
        int gj = (npp & 3) * 128 + c * 64 + (npp >> 2);
        g_bfrag[li] = L ? (bih1[gj] + bhh1[gj]) : (bih0[gj] + bhh0[gj]);
    }
}

// ---------------- K-loop: acc += Ahi*Bhi + Alo*Bhi + Ahi*Blo --------------------
template <int KS>
__device__ __forceinline__ void mma_block(float (&acc)[2][4][4],
                                          const uint32_t* __restrict__ bhi,
                                          const uint32_t* __restrict__ blo,
                                          uint32_t aHi, uint32_t aLo, int stride)
{
    #pragma unroll
    for (int ks = 0; ks < KS; ks++) {
        uint4 BH0 = *(const uint4*)(bhi + ks * 256);
        uint4 BH1 = *(const uint4*)(bhi + ks * 256 + 4);
        uint4 BL0 = *(const uint4*)(blo + ks * 256);
        uint4 BL1 = *(const uint4*)(blo + ks * 256 + 4);
        uint32_t BH[8] = {BH0.x, BH0.y, BH0.z, BH0.w, BH1.x, BH1.y, BH1.z, BH1.w};
        uint32_t BL[8] = {BL0.x, BL0.y, BL0.z, BL0.w, BL1.x, BL1.y, BL1.z, BL1.w};
        #pragma unroll
        for (int mf = 0; mf < 2; mf++) {
            uint32_t AH[4], AL[4];
            ldsm4(AH, aHi + mf * 16 * stride + ks * 32);
            ldsm4(AL, aLo + mf * 16 * stride + ks * 32);
            #pragma unroll
            for (int nf = 0; nf < 4; nf++) {
                mma16816(acc[mf][nf], AH, BH[nf * 2], BH[nf * 2 + 1]);
                mma16816(acc[mf][nf], AL, BH[nf * 2], BH[nf * 2 + 1]);
                mma16816(acc[mf][nf], AH, BL[nf * 2], BL[nf * 2 + 1]);
            }
        }
    }
}

__device__ __forceinline__ void init_bias(float (&acc)[2][4][4], int L, int c, int wn, int lane) {
    const float4* bp = (const float4*)(g_bfrag + (((L * 2 + c) * 8 + wn) * 32 + lane) * 8);
    float4 v0 = bp[0], v1 = bp[1];
    float bf[8] = {v0.x, v0.y, v0.z, v0.w, v1.x, v1.y, v1.z, v1.w};
    #pragma unroll
    for (int mf = 0; mf < 2; mf++)
        #pragma unroll
        for (int nf = 0; nf < 4; nf++) {
            acc[mf][nf][0] = bf[nf * 2];
            acc[mf][nf][1] = bf[nf * 2 + 1];
            acc[mf][nf][2] = bf[nf * 2];
            acc[mf][nf][3] = bf[nf * 2 + 1];
        }
}

__device__ __forceinline__ void epilogue(float (&acc)[2][4][4], float (&cst)[32], int cbase,
                                         int c, int wn, int quad, int qid, bool ev, char* smc,
                                         uint32_t wHi, uint32_t wLo, bool last,
                                         float* outH, float* outC, int b0)
{
    #pragma unroll
    for (int mf = 0; mf < 2; mf++)
        #pragma unroll
        for (int nf = 0; nf < 4; nf++) {
            float a0 = acc[mf][nf][0], a1 = acc[mf][nf][1];
            float a2 = acc[mf][nf][2], a3 = acc[mf][nf][3];
            float e1 = __shfl_xor_sync(0xffffffffu, ev ? a2 : a0, 1);
            float e2 = __shfl_xor_sync(0xffffffffu, ev ? a3 : a1, 1);
            float gi = ev ? a0 : e1;
            float gf = ev ? a1 : e2;
            float gg = ev ? e1 : a2;
            float go = ev ? e2 : a3;
            float cold = cst[cbase + mf * 4 + nf];
            float cn = sigm(gf) * cold + sigm(gi) * tanha(gg);
            cst[cbase + mf * 4 + nf] = cn;
            float h = sigm(go) * tanha(cn);
            int row = mf * 16 + quad + (ev ? 0 : 8);
            int j = c * 64 + wn * 8 + nf * 2 + (qid >> 1);
            __nv_bfloat16 hh = __float2bfloat16(h);
            __nv_bfloat16 hl = __float2bfloat16(h - __bfloat162float(hh));
            *(__nv_bfloat16*)(smc + wHi + row * HSTRIDE + j * 2) = hh;
            *(__nv_bfloat16*)(smc + wLo + row * HSTRIDE + j * 2) = hl;
            if (last) {
                outH[(size_t)(b0 + row) * HID + j] = h;
                outC[(size_t)(b0 + row) * HID + j] = cn;
            }
        }
}

// ---------------- main fused kernel ---------------------------------------------
__global__ __launch_bounds__(NT, 2)
void lstm_mma(const float* __restrict__ x,
              const float* __restrict__ fcw,
              const float* __restrict__ fcb,
              float* __restrict__ out)
{
    extern __shared__ __align__(128) char smc[];
    const uint32_t sb = smem_u32(smc);
    const int tid = threadIdx.x;
    const int wn = tid >> 5, lane = tid & 31;
    const int quad = lane >> 2, qid = lane & 3;
    const bool ev = !(qid & 1);
    const int b0 = blockIdx.x * MR;

    // zero all smem (x pad cols + initial h state)
    for (int i = tid; i < SMEM_BYTES / 4; i += NT) ((uint32_t*)smc)[i] = 0;
    __syncthreads();

    float cst[32];
    #pragma unroll
    for (int i = 0; i < 32; i++) cst[i] = 0.0f;

    float* outLog = out;
    float* outH = out + (size_t)BATCH * OUTDIM;
    float* outC = outH + 2ull * BATCH * HID;

    const uint32_t laneH = (lane & 15) * HSTRIDE + (lane >> 4) * 16;
    const uint32_t laneX = (lane & 15) * XSTRIDE + (lane >> 4) * 16;

    for (int t = 0; t < SEQ; t++) {
        const int pb = t & 1;
        // ---- stage x_t (bf16 hi/lo) ----
        for (int i = tid; i < MR * INDIM; i += NT) {
            int r = i / INDIM, k = i - r * INDIM;
            float v = x[(size_t)(b0 + r) * (SEQ * INDIM) + t * INDIM + k];
            __nv_bfloat16 hi = __float2bfloat16(v);
            __nv_bfloat16 lo = __float2bfloat16(v - __bfloat162float(hi));
            *(__nv_bfloat16*)(smc + SM_X + r * XSTRIDE + k * 2) = hi;
            *(__nv_bfloat16*)(smc + SM_X + MR * XSTRIDE + r * XSTRIDE + k * 2) = lo;
        }
        __syncthreads();

        const bool last = (t == SEQ - 1);
        const uint32_t h0rHi = HT_OFF(0, pb, 0),     h0rLo = HT_OFF(0, pb, 1);
        const uint32_t h0wHi = HT_OFF(0, pb ^ 1, 0), h0wLo = HT_OFF(0, pb ^ 1, 1);
        const uint32_t h1rHi = HT_OFF(1, pb, 0),     h1rLo = HT_OFF(1, pb, 1);
        const uint32_t h1wHi = HT_OFF(1, pb ^ 1, 0), h1wLo = HT_OFF(1, pb ^ 1, 1);

        // ============ LAYER 0 ============
        #pragma unroll
        for (int c = 0; c < 2; c++) {
            float acc[2][4][4];
            init_bias(acc, 0, c, wn, lane);
            mma_block<2>(acc, g_Whi + SEC_IH0 + ((c * 8 + wn) * 2) * 256 + lane * 8,
                              g_Wlo + SEC_IH0 + ((c * 8 + wn) * 2) * 256 + lane * 8,
                         sb + SM_X + laneX, sb + SM_X + MR * XSTRIDE + laneX, XSTRIDE);
            mma_block<8>(acc, g_Whi + SEC_HH0 + ((c * 8 + wn) * 8) * 256 + lane * 8,
                              g_Wlo + SEC_HH0 + ((c * 8 + wn) * 8) * 256 + lane * 8,
                         sb + h0rHi + laneH, sb + h0rLo + laneH, HSTRIDE);
            epilogue(acc, cst, c * 8, c, wn, quad, qid, ev, smc,
                     h0wHi, h0wLo, last, outH, outC, b0);
        }
        __syncthreads();   // h0(new) complete before L1 reads it

        // ============ LAYER 1 ============
        #pragma unroll
        for (int c = 0; c < 2; c++) {
            float acc[2][4][4];
            init_bias(acc, 1, c, wn, lane);
            mma_block<8>(acc, g_Whi + SEC_IH1 + ((c * 8 + wn) * 8) * 256 + lane * 8,
                              g_Wlo + SEC_IH1 + ((c * 8 + wn) * 8) * 256 + lane * 8,
                         sb + h0wHi + laneH, sb + h0wLo + laneH, HSTRIDE);
            mma_block<8>(acc, g_Whi + SEC_HH1 + ((c * 8 + wn) * 8) * 256 + lane * 8,
                              g_Wlo + SEC_HH1 + ((c * 8 + wn) * 8) * 256 + lane * 8,
                         sb + h1rHi + laneH, sb + h1rLo + laneH, HSTRIDE);
            epilogue(acc, cst, 16 + c * 8, c, wn, quad, qid, ev, smc,
                     h1wHi, h1wLo, last, outH + (size_t)BATCH * HID,
                     outC + (size_t)BATCH * HID, b0);
        }
        __syncthreads();   // h1(new) + all writes done before next stage/FC
    }

    // ---- FC head from final h1 (buffer 0 after t=27) ----
    {
        const char* hHi = smc + HT_OFF(1, 0, 0);
        const char* hLo = smc + HT_OFF(1, 0, 1);
        for (int i = tid; i < MR * OUTDIM; i += NT) {
            int r = i / OUTDIM, o = i - r * OUTDIM;
            float s = fcb[o];
            #pragma unroll 4
            for (int j = 0; j < HID; j++) {
                float hv = __bfloat162float(*(const __nv_bfloat16*)(hHi + r * HSTRIDE + j * 2))
                         + __bfloat162float(*(const __nv_bfloat16*)(hLo + r * HSTRIDE + j * 2));
                s += hv * fcw[o * HID + j];
            }
            outLog[(size_t)(b0 + r) * OUTDIM + o] = s;
        }
    }
}

// ---------------- launch ----------------------------------------------------------
extern "C" void kernel_launch(void* const* d_in, const int* in_sizes, int n_in,
                              void* d_out, int out_size) {
    const float* x    = (const float*)d_in[0];
    const float* wih0 = (const float*)d_in[1];
    const float* whh0 = (const float*)d_in[2];
    const float* bih0 = (const float*)d_in[3];
    const float* bhh0 = (const float*)d_in[4];
    const float* wih1 = (const float*)d_in[5];
    const float* whh1 = (const float*)d_in[6];
    const float* bih1 = (const float*)d_in[7];
    const float* bhh1 = (const float*)d_in[8];
    const float* fcw  = (const float*)d_in[9];
    const float* fcb  = (const float*)d_in[10];

    lstm_prep<<<(W_TOTAL + 8192 + 255) / 256, 256>>>(wih0, whh0, bih0, bhh0,
                                                     wih1, whh1, bih1, bhh1);

    cudaFuncSetAttribute(lstm_mma, cudaFuncAttributeMaxDynamicSharedMemorySize, SMEM_BYTES);
    lstm_mma<<<BATCH / MR, NT, SMEM_BYTES>>>(x, fcw, fcb, (float*)d_out);
}

// round 10
// speedup vs baseline: 4.3707x; 1.3182x over previous
#include <cuda_runtime.h>
#include <cuda_fp16.h>
#include <stdint.h>
#include <math.h>

#define BATCH  16384
#define HID    128
#define SEQ    28
#define INDIM  28
#define OUTDIM 10
#define MR     32       // batch rows per CTA (2 CTAs/SM)
#define NT     256
#define HSTRIDE 272     // h tile row stride bytes (136 fp16) — ldsm conflict-free
#define XSTRIDE 80      // x tile row stride bytes
#define HT_SZ  (MR * HSTRIDE)            // 8704 B per h tile
#define SM_X   (8 * HT_SZ)               // x tiles after 8 h tiles
#define XBUF_SZ (2 * MR * XSTRIDE)       // one x buffer (hi+lo)
#define SMEM_BYTES (SM_X + 2 * XBUF_SZ)  // 79872

// h tile offset: layer L, buffer b, precision p (0=hi,1=lo)
#define HT_OFF(L, b, p) ((((L) * 2 + (b)) * 2 + (p)) * HT_SZ)

// ---- prepped weights: exact mma.m16n8k16 B-fragment order, single fp16 ----
// layout per matrix section: [(c*8+wn)*KS + ks][lane][8 regs(uint32)]
// reg r = nf*2 + b : packed fp16 pair (k0, k0+1), k0 = ks*16 + (lane&3)*2 + b*8,
//                    n'' = wn*32 + nf*8 + lane/4,  n = (n''&3)*128 + c*64 + (n''>>2)
#define SEC_IH0 0
#define SEC_HH0 8192
#define SEC_IH1 40960
#define SEC_HH1 73728
#define W_TOTAL 106496
__device__ uint32_t g_W[W_TOTAL];
__device__ float    g_bfrag[2 * 2 * 8 * 32 * 8];   // [L][c][wn][lane][8]

// ---------------- helpers ----------------
__device__ __forceinline__ uint32_t smem_u32(const void* p) {
    uint32_t a;
    asm("{ .reg .u64 t; cvta.to.shared.u64 t, %1; cvt.u32.u64 %0, t; }" : "=r"(a) : "l"(p));
    return a;
}
__device__ __forceinline__ void ldsm4(uint32_t* r, uint32_t addr) {
    asm volatile("ldmatrix.sync.aligned.m8n8.x4.shared.b16 {%0,%1,%2,%3}, [%4];"
                 : "=r"(r[0]), "=r"(r[1]), "=r"(r[2]), "=r"(r[3]) : "r"(addr));
}
__device__ __forceinline__ void mma16816(float* d, const uint32_t* a, uint32_t b0, uint32_t b1) {
    asm volatile("mma.sync.aligned.m16n8k16.row.col.f32.f16.f16.f32 "
                 "{%0,%1,%2,%3}, {%4,%5,%6,%7}, {%8,%9}, {%0,%1,%2,%3};"
                 : "+f"(d[0]), "+f"(d[1]), "+f"(d[2]), "+f"(d[3])
                 : "r"(a[0]), "r"(a[1]), "r"(a[2]), "r"(a[3]), "r"(b0), "r"(b1));
}
__device__ __forceinline__ float sigm(float x) {
    float e = __expf(-x);
    return __fdividef(1.0f, 1.0f + e);
}
__device__ __forceinline__ float tanha(float x) {
    float e = __expf(2.0f * x);
    return 1.0f - __fdividef(2.0f, e + 1.0f);
}
__device__ __forceinline__ uint32_t packh(__half a, __half b) {
    return (uint32_t)__half_as_ushort(a) | ((uint32_t)__half_as_ushort(b) << 16);
}

// ---------------- prep: weights -> fp16 B-fragments, bias -> C-fragments -------
__global__ void lstm_prep(const float* __restrict__ wih0, const float* __restrict__ whh0,
                          const float* __restrict__ bih0, const float* __restrict__ bhh0,
                          const float* __restrict__ wih1, const float* __restrict__ whh1,
                          const float* __restrict__ bih1, const float* __restrict__ bhh1) {
    int i = blockIdx.x * blockDim.x + threadIdx.x;
    if (i < W_TOTAL) {
        const float* W; int realK, KS, li;
        if      (i < SEC_HH0) { W = wih0; realK = INDIM; KS = 2; li = i; }
        else if (i < SEC_IH1) { W = whh0; realK = 128;   KS = 8; li = i - SEC_HH0; }
        else if (i < SEC_HH1) { W = wih1; realK = 128;   KS = 8; li = i - SEC_IH1; }
        else                  { W = whh1; realK = 128;   KS = 8; li = i - SEC_HH1; }
        int reg = li & 7, lane = (li >> 3) & 31;
        int ks = (li >> 8) % KS, rest = (li >> 8) / KS;
        int wn = rest & 7, c = rest >> 3;
        int nf = reg >> 1, b = reg & 1;
        int npp = wn * 32 + nf * 8 + (lane >> 2);
        int n = (npp & 3) * 128 + c * 64 + (npp >> 2);
        int k0 = ks * 16 + (lane & 3) * 2 + b * 8;
        float w0 = (k0     < realK) ? W[n * realK + k0]     : 0.0f;
        float w1 = (k0 + 1 < realK) ? W[n * realK + k0 + 1] : 0.0f;
        g_W[i] = packh(__float2half_rn(w0), __float2half_rn(w1));
    } else if (i < W_TOTAL + 8192) {
        int li = i - W_TOTAL;
        int reg = li & 7, lane = (li >> 3) & 31, wn = (li >> 8) & 7, c = (li >> 11) & 1, L = li >> 12;
        int npp = wn * 32 + (reg >> 1) * 8 + (lane & 3) * 2 + (reg & 1);
        int gj = (npp & 3) * 128 + c * 64 + (npp >> 2);
        g_bfrag[li] = L ? (bih1[gj] + bhh1[gj]) : (bih0[gj] + bhh0[gj]);
    }
}

// ---------------- K-loop: acc += Ahi*W + Alo*W (2-pass fp16) --------------------
template <int KS>
__device__ __forceinline__ void mma_block(float (&acc)[2][4][4],
                                          const uint32_t* __restrict__ bw,
                                          uint32_t aHi, uint32_t aLo, int stride)
{
    #pragma unroll
    for (int ks = 0; ks < KS; ks++) {
        uint4 B0 = *(const uint4*)(bw + ks * 256);
        uint4 B1 = *(const uint4*)(bw + ks * 256 + 4);
        uint32_t B[8] = {B0.x, B0.y, B0.z, B0.w, B1.x, B1.y, B1.z, B1.w};
        #pragma unroll
        for (int mf = 0; mf < 2; mf++) {
            uint32_t AH[4], AL[4];
            ldsm4(AH, aHi + mf * 16 * stride + ks * 32);
            ldsm4(AL, aLo + mf * 16 * stride + ks * 32);
            #pragma unroll
            for (int nf = 0; nf < 4; nf++) {
                mma16816(acc[mf][nf], AH, B[nf * 2], B[nf * 2 + 1]);
                mma16816(acc[mf][nf], AL, B[nf * 2], B[nf * 2 + 1]);
            }
        }
    }
}

__device__ __forceinline__ void init_bias(float (&acc)[2][4][4], int L, int c, int wn, int lane) {
    const float4* bp = (const float4*)(g_bfrag + (((L * 2 + c) * 8 + wn) * 32 + lane) * 8);
    float4 v0 = bp[0], v1 = bp[1];
    float bf[8] = {v0.x, v0.y, v0.z, v0.w, v1.x, v1.y, v1.z, v1.w};
    #pragma unroll
    for (int mf = 0; mf < 2; mf++)
        #pragma unroll
        for (int nf = 0; nf < 4; nf++) {
            acc[mf][nf][0] = bf[nf * 2];
            acc[mf][nf][1] = bf[nf * 2 + 1];
            acc[mf][nf][2] = bf[nf * 2];
            acc[mf][nf][3] = bf[nf * 2 + 1];
        }
}

__device__ __forceinline__ void epilogue(float (&acc)[2][4][4], float (&cst)[32], int cbase,
                                         int c, int wn, int quad, int qid, bool ev, char* smc,
                                         uint32_t wHi, uint32_t wLo, bool last,
                                         float* outH, float* outC, int b0)
{
    #pragma unroll
    for (int mf = 0; mf < 2; mf++)
        #pragma unroll
        for (int nf = 0; nf < 4; nf++) {
            float a0 = acc[mf][nf][0], a1 = acc[mf][nf][1];
            float a2 = acc[mf][nf][2], a3 = acc[mf][nf][3];
            float e1 = __shfl_xor_sync(0xffffffffu, ev ? a2 : a0, 1);
            float e2 = __shfl_xor_sync(0xffffffffu, ev ? a3 : a1, 1);
            float gi = ev ? a0 : e1;
            float gf = ev ? a1 : e2;
            float gg = ev ? e1 : a2;
            float go = ev ? e2 : a3;
            float cold = cst[cbase + mf * 4 + nf];
            float cn = sigm(gf) * cold + sigm(gi) * tanha(gg);
            cst[cbase + mf * 4 + nf] = cn;
            float h = sigm(go) * tanha(cn);
            int row = mf * 16 + quad + (ev ? 0 : 8);
            int j = c * 64 + wn * 8 + nf * 2 + (qid >> 1);
            __half hh = __float2half_rn(h);
            __half hl = __float2half_rn(h - __half2float(hh));
            *(__half*)(smc + wHi + row * HSTRIDE + j * 2) = hh;
            *(__half*)(smc + wLo + row * HSTRIDE + j * 2) = hl;
            if (last) {
                outH[(size_t)(b0 + row) * HID + j] = h;
                outC[(size_t)(b0 + row) * HID + j] = cn;
            }
        }
}

// ---------------- main fused kernel ---------------------------------------------
__global__ __launch_bounds__(NT, 2)
void lstm_mma(const float* __restrict__ x,
              const float* __restrict__ fcw,
              const float* __restrict__ fcb,
              float* __restrict__ out)
{
    extern __shared__ __align__(128) char smc[];
    const uint32_t sb = smem_u32(smc);
    const int tid = threadIdx.x;
    const int wn = tid >> 5, lane = tid & 31;
    const int quad = lane >> 2, qid = lane & 3;
    const bool ev = !(qid & 1);
    const int b0 = blockIdx.x * MR;

    // zero all smem (x pad cols + initial h state)
    for (int i = tid; i < SMEM_BYTES / 4; i += NT) ((uint32_t*)smc)[i] = 0;
    __syncthreads();

    // stage x(0) into buffer 0
    for (int i = tid; i < MR * INDIM; i += NT) {
        int r = i / INDIM, k = i - r * INDIM;
        float v = x[(size_t)(b0 + r) * (SEQ * INDIM) + 0 * INDIM + k];
        __half hi = __float2half_rn(v);
        __half lo = __float2half_rn(v - __half2float(hi));
        *(__half*)(smc + SM_X + r * XSTRIDE + k * 2) = hi;
        *(__half*)(smc + SM_X + MR * XSTRIDE + r * XSTRIDE + k * 2) = lo;
    }
    __syncthreads();

    float cst[32];
    #pragma unroll
    for (int i = 0; i < 32; i++) cst[i] = 0.0f;

    float* outLog = out;
    float* outH = out + (size_t)BATCH * OUTDIM;
    float* outC = outH + 2ull * BATCH * HID;

    const uint32_t laneH = (lane & 15) * HSTRIDE + (lane >> 4) * 16;
    const uint32_t laneX = (lane & 15) * XSTRIDE + (lane >> 4) * 16;

    for (int t = 0; t < SEQ; t++) {
        const int pb = t & 1;
        const bool last = (t == SEQ - 1);
        const uint32_t xb = SM_X + pb * XBUF_SZ;
        const uint32_t h0rHi = HT_OFF(0, pb, 0),     h0rLo = HT_OFF(0, pb, 1);
        const uint32_t h0wHi = HT_OFF(0, pb ^ 1, 0), h0wLo = HT_OFF(0, pb ^ 1, 1);
        const uint32_t h1rHi = HT_OFF(1, pb, 0),     h1rLo = HT_OFF(1, pb, 1);
        const uint32_t h1wHi = HT_OFF(1, pb ^ 1, 0), h1wLo = HT_OFF(1, pb ^ 1, 1);

        // ============ LAYER 0 ============
        #pragma unroll
        for (int c = 0; c < 2; c++) {
            float acc[2][4][4];
            init_bias(acc, 0, c, wn, lane);
            mma_block<2>(acc, g_W + SEC_IH0 + ((c * 8 + wn) * 2) * 256 + lane * 8,
                         sb + xb + laneX, sb + xb + MR * XSTRIDE + laneX, XSTRIDE);
            mma_block<8>(acc, g_W + SEC_HH0 + ((c * 8 + wn) * 8) * 256 + lane * 8,
                         sb + h0rHi + laneH, sb + h0rLo + laneH, HSTRIDE);
            epilogue(acc, cst, c * 8, c, wn, quad, qid, ev, smc,
                     h0wHi, h0wLo, last, outH, outC, b0);
        }

        // ---- stage x(t+1) into the other buffer (ordered by the barrier below) ----
        if (t + 1 < SEQ) {
            const uint32_t xn = SM_X + (pb ^ 1) * XBUF_SZ;
            for (int i = tid; i < MR * INDIM; i += NT) {
                int r = i / INDIM, k = i - r * INDIM;
                float v = x[(size_t)(b0 + r) * (SEQ * INDIM) + (t + 1) * INDIM + k];
                __half hi = __float2half_rn(v);
                __half lo = __float2half_rn(v - __half2float(hi));
                *(__half*)(smc + xn + r * XSTRIDE + k * 2) = hi;
                *(__half*)(smc + xn + MR * XSTRIDE + r * XSTRIDE + k * 2) = lo;
            }
        }
        __syncthreads();   // h0(new) complete + x(t+1) staged

        // ============ LAYER 1 ============
        #pragma unroll
        for (int c = 0; c < 2; c++) {
            float acc[2][4][4];
            init_bias(acc, 1, c, wn, lane);
            mma_block<8>(acc, g_W + SEC_IH1 + ((c * 8 + wn) * 8) * 256 + lane * 8,
                         sb + h0wHi + laneH, sb + h0wLo + laneH, HSTRIDE);
            mma_block<8>(acc, g_W + SEC_HH1 + ((c * 8 + wn) * 8) * 256 + lane * 8,
                         sb + h1rHi + laneH, sb + h1rLo + laneH, HSTRIDE);
            epilogue(acc, cst, 16 + c * 8, c, wn, quad, qid, ev, smc,
                     h1wHi, h1wLo, last, outH + (size_t)BATCH * HID,
                     outC + (size_t)BATCH * HID, b0);
        }
        __syncthreads();   // h1(new) done before next step reads it
    }

    // ---- FC head from final h1 (buffer 0 after t=27) ----
    {
        const char* hHi = smc + HT_OFF(1, 0, 0);
        const char* hLo = smc + HT_OFF(1, 0, 1);
        for (int i = tid; i < MR * OUTDIM; i += NT) {
            int r = i / OUTDIM, o = i - r * OUTDIM;
            float s = fcb[o];
            #pragma unroll 4
            for (int j = 0; j < HID; j++) {
                float hv = __half2float(*(const __half*)(hHi + r * HSTRIDE + j * 2))
                         + __half2float(*(const __half*)(hLo + r * HSTRIDE + j * 2));
                s += hv * fcw[o * HID + j];
            }
            outLog[(size_t)(b0 + r) * OUTDIM + o] = s;
        }
    }
}

// ---------------- launch ----------------------------------------------------------
extern "C" void kernel_launch(void* const* d_in, const int* in_sizes, int n_in,
                              void* d_out, int out_size) {
    const float* x    = (const float*)d_in[0];
    const float* wih0 = (const float*)d_in[1];
    const float* whh0 = (const float*)d_in[2];
    const float* bih0 = (const float*)d_in[3];
    const float* bhh0 = (const float*)d_in[4];
    const float* wih1 = (const float*)d_in[5];
    const float* whh1 = (const float*)d_in[6];
    const float* bih1 = (const float*)d_in[7];
    const float* bhh1 = (const float*)d_in[8];
    const float* fcw  = (const float*)d_in[9];
    const float* fcb  = (const float*)d_in[10];

    lstm_prep<<<(W_TOTAL + 8192 + 255) / 256, 256>>>(wih0, whh0, bih0, bhh0,
                                                     wih1, whh1, bih1, bhh1);

    cudaFuncSetAttribute(lstm_mma, cudaFuncAttributeMaxDynamicSharedMemorySize, SMEM_BYTES);
    lstm_mma<<<BATCH / MR, NT, SMEM_BYTES>>>(x, fcw, fcb, (float*)d_out);
}

// round 11
// speedup vs baseline: 5.7092x; 1.3062x over previous
#include <cuda_runtime.h>
#include <cuda_fp16.h>
#include <stdint.h>
#include <math.h>

#define BATCH  16384
#define HID    128
#define SEQ    28
#define INDIM  28
#define OUTDIM 10
#define MR     32       // batch rows per CTA (2 CTAs/SM)
#define NT     256
#define HSTRIDE 272     // h tile row stride bytes (136 fp16) — ldsm conflict-free
#define XSTRIDE 80      // x tile row stride bytes
#define HT_SZ  (MR * HSTRIDE)            // 8704 B per h tile
#define SM_X   (4 * HT_SZ)               // x tiles after 4 h tiles (L x buf)
#define XBUF_SZ (MR * XSTRIDE)           // one x buffer
#define SMEM_BYTES (SM_X + 2 * XBUF_SZ)  // 39936

// h tile offset: layer L, buffer b
#define HT_OFF(L, b) (((L) * 2 + (b)) * HT_SZ)

// ---- prepped weights: exact mma.m16n8k16 B-fragment order, single fp16 ----
// layout per matrix section: [(c*8+wn)*KS + ks][lane][8 regs(uint32)]
// reg r = nf*2 + b : packed fp16 pair (k0, k0+1), k0 = ks*16 + (lane&3)*2 + b*8,
//                    n'' = wn*32 + nf*8 + lane/4,  n = (n''&3)*128 + c*64 + (n''>>2)
#define SEC_IH0 0
#define SEC_HH0 8192
#define SEC_IH1 40960
#define SEC_HH1 73728
#define W_TOTAL 106496
__device__ uint32_t g_W[W_TOTAL];
__device__ float    g_bfrag[2 * 2 * 8 * 32 * 8];   // [L][c][wn][lane][8]

// ---------------- helpers ----------------
__device__ __forceinline__ uint32_t smem_u32(const void* p) {
    uint32_t a;
    asm("{ .reg .u64 t; cvta.to.shared.u64 t, %1; cvt.u32.u64 %0, t; }" : "=r"(a) : "l"(p));
    return a;
}
__device__ __forceinline__ void ldsm4(uint32_t* r, uint32_t addr) {
    asm volatile("ldmatrix.sync.aligned.m8n8.x4.shared.b16 {%0,%1,%2,%3}, [%4];"
                 : "=r"(r[0]), "=r"(r[1]), "=r"(r[2]), "=r"(r[3]) : "r"(addr));
}
__device__ __forceinline__ void mma16816(float* d, const uint32_t* a, uint32_t b0, uint32_t b1) {
    asm volatile("mma.sync.aligned.m16n8k16.row.col.f32.f16.f16.f32 "
                 "{%0,%1,%2,%3}, {%4,%5,%6,%7}, {%8,%9}, {%0,%1,%2,%3};"
                 : "+f"(d[0]), "+f"(d[1]), "+f"(d[2]), "+f"(d[3])
                 : "r"(a[0]), "r"(a[1]), "r"(a[2]), "r"(a[3]), "r"(b0), "r"(b1));
}
__device__ __forceinline__ float sigm(float x) {
    float e = __expf(-x);
    return __fdividef(1.0f, 1.0f + e);
}
__device__ __forceinline__ float tanha(float x) {
    float e = __expf(2.0f * x);
    return 1.0f - __fdividef(2.0f, e + 1.0f);
}
__device__ __forceinline__ uint32_t packh(__half a, __half b) {
    return (uint32_t)__half_as_ushort(a) | ((uint32_t)__half_as_ushort(b) << 16);
}

// ---------------- prep: weights -> fp16 B-fragments, bias -> C-fragments -------
__global__ void lstm_prep(const float* __restrict__ wih0, const float* __restrict__ whh0,
                          const float* __restrict__ bih0, const float* __restrict__ bhh0,
                          const float* __restrict__ wih1, const float* __restrict__ whh1,
                          const float* __restrict__ bih1, const float* __restrict__ bhh1) {
    int i = blockIdx.x * blockDim.x + threadIdx.x;
    if (i < W_TOTAL) {
        const float* W; int realK, KS, li;
        if      (i < SEC_HH0) { W = wih0; realK = INDIM; KS = 2; li = i; }
        else if (i < SEC_IH1) { W = whh0; realK = 128;   KS = 8; li = i - SEC_HH0; }
        else if (i < SEC_HH1) { W = wih1; realK = 128;   KS = 8; li = i - SEC_IH1; }
        else                  { W = whh1; realK = 128;   KS = 8; li = i - SEC_HH1; }
        int reg = li & 7, lane = (li >> 3) & 31;
        int ks = (li >> 8) % KS, rest = (li >> 8) / KS;
        int wn = rest & 7, c = rest >> 3;
        int nf = reg >> 1, b = reg & 1;
        int npp = wn * 32 + nf * 8 + (lane >> 2);
        int n = (npp & 3) * 128 + c * 64 + (npp >> 2);
        int k0 = ks * 16 + (lane & 3) * 2 + b * 8;
        float w0 = (k0     < realK) ? W[n * realK + k0]     : 0.0f;
        float w1 = (k0 + 1 < realK) ? W[n * realK + k0 + 1] : 0.0f;
        g_W[i] = packh(__float2half_rn(w0), __float2half_rn(w1));
    } else if (i < W_TOTAL + 8192) {
        int li = i - W_TOTAL;
        int reg = li & 7, lane = (li >> 3) & 31, wn = (li >> 8) & 7, c = (li >> 11) & 1, L = li >> 12;
        int npp = wn * 32 + (reg >> 1) * 8 + (lane & 3) * 2 + (reg & 1);
        int gj = (npp & 3) * 128 + c * 64 + (npp >> 2);
        g_bfrag[li] = L ? (bih1[gj] + bhh1[gj]) : (bih0[gj] + bhh0[gj]);
    }
}

// ---------------- K-loop: acc += A*W (single-pass fp16) -------------------------
template <int KS>
__device__ __forceinline__ void mma_block(float (&acc)[2][4][4],
                                          const uint32_t* __restrict__ bw,
                                          uint32_t aBase, int stride)
{
    #pragma unroll
    for (int ks = 0; ks < KS; ks++) {
        uint4 B0 = *(const uint4*)(bw + ks * 256);
        uint4 B1 = *(const uint4*)(bw + ks * 256 + 4);
        uint32_t B[8] = {B0.x, B0.y, B0.z, B0.w, B1.x, B1.y, B1.z, B1.w};
        #pragma unroll
        for (int mf = 0; mf < 2; mf++) {
            uint32_t A[4];
            ldsm4(A, aBase + mf * 16 * stride + ks * 32);
            #pragma unroll
            for (int nf = 0; nf < 4; nf++)
                mma16816(acc[mf][nf], A, B[nf * 2], B[nf * 2 + 1]);
        }
    }
}

__device__ __forceinline__ void init_bias(float (&acc)[2][4][4], int L, int c, int wn, int lane) {
    const float4* bp = (const float4*)(g_bfrag + (((L * 2 + c) * 8 + wn) * 32 + lane) * 8);
    float4 v0 = bp[0], v1 = bp[1];
    float bf[8] = {v0.x, v0.y, v0.z, v0.w, v1.x, v1.y, v1.z, v1.w};
    #pragma unroll
    for (int mf = 0; mf < 2; mf++)
        #pragma unroll
        for (int nf = 0; nf < 4; nf++) {
            acc[mf][nf][0] = bf[nf * 2];
            acc[mf][nf][1] = bf[nf * 2 + 1];
            acc[mf][nf][2] = bf[nf * 2];
            acc[mf][nf][3] = bf[nf * 2 + 1];
        }
}

__device__ __forceinline__ void epilogue(float (&acc)[2][4][4], float (&cst)[32], int cbase,
                                         int c, int wn, int quad, int qid, bool ev, char* smc,
                                         uint32_t wTile, bool last,
                                         float* outH, float* outC, int b0)
{
    #pragma unroll
    for (int mf = 0; mf < 2; mf++)
        #pragma unroll
        for (int nf = 0; nf < 4; nf++) {
            float a0 = acc[mf][nf][0], a1 = acc[mf][nf][1];
            float a2 = acc[mf][nf][2], a3 = acc[mf][nf][3];
            float e1 = __shfl_xor_sync(0xffffffffu, ev ? a2 : a0, 1);
            float e2 = __shfl_xor_sync(0xffffffffu, ev ? a3 : a1, 1);
            float gi = ev ? a0 : e1;
            float gf = ev ? a1 : e2;
            float gg = ev ? e1 : a2;
            float go = ev ? e2 : a3;
            float cold = cst[cbase + mf * 4 + nf];
            float cn = sigm(gf) * cold + sigm(gi) * tanha(gg);
            cst[cbase + mf * 4 + nf] = cn;
            float h = sigm(go) * tanha(cn);
            int row = mf * 16 + quad + (ev ? 0 : 8);
            int j = c * 64 + wn * 8 + nf * 2 + (qid >> 1);
            *(__half*)(smc + wTile + row * HSTRIDE + j * 2) = __float2half_rn(h);
            if (last) {
                outH[(size_t)(b0 + row) * HID + j] = h;
                outC[(size_t)(b0 + row) * HID + j] = cn;
            }
        }
}

// ---------------- main fused kernel ---------------------------------------------
__global__ __launch_bounds__(NT, 2)
void lstm_mma(const float* __restrict__ x,
              const float* __restrict__ fcw,
              const float* __restrict__ fcb,
              float* __restrict__ out)
{
    extern __shared__ __align__(128) char smc[];
    const uint32_t sb = smem_u32(smc);
    const int tid = threadIdx.x;
    const int wn = tid >> 5, lane = tid & 31;
    const int quad = lane >> 2, qid = lane & 3;
    const bool ev = !(qid & 1);
    const int b0 = blockIdx.x * MR;

    // zero all smem (x pad cols + initial h state)
    for (int i = tid; i < SMEM_BYTES / 4; i += NT) ((uint32_t*)smc)[i] = 0;
    __syncthreads();

    // stage x(0) into buffer 0
    for (int i = tid; i < MR * INDIM; i += NT) {
        int r = i / INDIM, k = i - r * INDIM;
        float v = x[(size_t)(b0 + r) * (SEQ * INDIM) + k];
        *(__half*)(smc + SM_X + r * XSTRIDE + k * 2) = __float2half_rn(v);
    }
    __syncthreads();

    float cst[32];
    #pragma unroll
    for (int i = 0; i < 32; i++) cst[i] = 0.0f;

    float* outLog = out;
    float* outH = out + (size_t)BATCH * OUTDIM;
    float* outC = outH + 2ull * BATCH * HID;

    const uint32_t laneH = (lane & 15) * HSTRIDE + (lane >> 4) * 16;
    const uint32_t laneX = (lane & 15) * XSTRIDE + (lane >> 4) * 16;

    for (int t = 0; t < SEQ; t++) {
        const int pb = t & 1;
        const bool last = (t == SEQ - 1);
        const uint32_t xb  = SM_X + pb * XBUF_SZ;
        const uint32_t h0r = HT_OFF(0, pb), h0w = HT_OFF(0, pb ^ 1);
        const uint32_t h1r = HT_OFF(1, pb), h1w = HT_OFF(1, pb ^ 1);

        // ============ LAYER 0 ============
        #pragma unroll
        for (int c = 0; c < 2; c++) {
            float acc[2][4][4];
            init_bias(acc, 0, c, wn, lane);
            mma_block<2>(acc, g_W + SEC_IH0 + ((c * 8 + wn) * 2) * 256 + lane * 8,
                         sb + xb + laneX, XSTRIDE);
            mma_block<8>(acc, g_W + SEC_HH0 + ((c * 8 + wn) * 8) * 256 + lane * 8,
                         sb + h0r + laneH, HSTRIDE);
            epilogue(acc, cst, c * 8, c, wn, quad, qid, ev, smc,
                     h0w, last, outH, outC, b0);
        }

        // ---- stage x(t+1) into the other buffer (ordered by the barrier below) ----
        if (t + 1 < SEQ) {
            const uint32_t xn = SM_X + (pb ^ 1) * XBUF_SZ;
            for (int i = tid; i < MR * INDIM; i += NT) {
                int r = i / INDIM, k = i - r * INDIM;
                float v = x[(size_t)(b0 + r) * (SEQ * INDIM) + (t + 1) * INDIM + k];
                *(__half*)(smc + xn + r * XSTRIDE + k * 2) = __float2half_rn(v);
            }
        }
        __syncthreads();   // h0(new) complete + x(t+1) staged

        // ============ LAYER 1 ============
        #pragma unroll
        for (int c = 0; c < 2; c++) {
            float acc[2][4][4];
            init_bias(acc, 1, c, wn, lane);
            mma_block<8>(acc, g_W + SEC_IH1 + ((c * 8 + wn) * 8) * 256 + lane * 8,
                         sb + h0w + laneH, HSTRIDE);
            mma_block<8>(acc, g_W + SEC_HH1 + ((c * 8 + wn) * 8) * 256 + lane * 8,
                         sb + h1r + laneH, HSTRIDE);
            epilogue(acc, cst, 16 + c * 8, c, wn, quad, qid, ev, smc,
                     h1w, last, outH + (size_t)BATCH * HID,
                     outC + (size_t)BATCH * HID, b0);
        }
        __syncthreads();   // h1(new) done before next step reads it
    }

    // ---- FC head from final h1 (buffer 0 after t=27) ----
    {
        const char* hT = smc + HT_OFF(1, 0);
        for (int i = tid; i < MR * OUTDIM; i += NT) {
            int r = i / OUTDIM, o = i - r * OUTDIM;
            float s = fcb[o];
            #pragma unroll 4
            for (int j = 0; j < HID; j++) {
                float hv = __half2float(*(const __half*)(hT + r * HSTRIDE + j * 2));
                s += hv * fcw[o * HID + j];
            }
            outLog[(size_t)(b0 + r) * OUTDIM + o] = s;
        }
    }
}

// ---------------- launch ----------------------------------------------------------
extern "C" void kernel_launch(void* const* d_in, const int* in_sizes, int n_in,
                              void* d_out, int out_size) {
    const float* x    = (const float*)d_in[0];
    const float* wih0 = (const float*)d_in[1];
    const float* whh0 = (const float*)d_in[2];
    const float* bih0 = (const float*)d_in[3];
    const float* bhh0 = (const float*)d_in[4];
    const float* wih1 = (const float*)d_in[5];
    const float* whh1 = (const float*)d_in[6];
    const float* bih1 = (const float*)d_in[7];
    const float* bhh1 = (const float*)d_in[8];
    const float* fcw  = (const float*)d_in[9];
    const float* fcb  = (const float*)d_in[10];

    lstm_prep<<<(W_TOTAL + 8192 + 255) / 256, 256>>>(wih0, whh0, bih0, bhh0,
                                                     wih1, whh1, bih1, bhh1);

    cudaFuncSetAttribute(lstm_mma, cudaFuncAttributeMaxDynamicSharedMemorySize, SMEM_BYTES);
    lstm_mma<<<BATCH / MR, NT, SMEM_BYTES>>>(x, fcw, fcb, (float*)d_out);
}